// round 5
// baseline (speedup 1.0000x reference)
#include <cuda_runtime.h>

// delta_layer: out[b,t,:] = [ x, delta(x), delta(delta(x)) ]
// delta(y)[t] = 0.5*(y[c(t+1)]-y[c(t-1)]) + 0.25*(y[c(t+2)]-y[c(t-2)]), c = clamp [0,T-1]
// Shapes fixed: B=32, T=4096, D=256, window=2.
//
// float2 granularity, 9-deep register ring, fused 9-tap double-delta:
//   dd(t) = 0.0625(x[t-4]+x[t+4]) + 0.25(x[t-3]+x[t+3]) + 0.25(x[t-2]+x[t+2])
//         - 0.25(x[t-1]+x[t+1]) - 0.625 x[t]
// Round-5 change: time loop processed in groups of 4 with a 4-row prefetch
// batch issued before each group -> per-warp MLP 4, use-distance ~4 iters.

#define B_N 32
#define T_N 4096
#define D2_N 128           // 256 floats / 2
#define OD2_N 384          // 768 floats / 2
#define L_N 32             // rows per thread chunk
#define G_N 4              // group size (prefetch batch)
#define CHUNKS (T_N / L_N) // 128

__device__ __forceinline__ float2 f2_delta(float2 m2, float2 m1, float2 p1, float2 p2) {
    float2 r;
    r.x = 0.5f * (p1.x - m1.x) + 0.25f * (p2.x - m2.x);
    r.y = 0.5f * (p1.y - m1.y) + 0.25f * (p2.y - m2.y);
    return r;
}

__device__ __forceinline__ float dd9(float a0, float a1, float a2, float a3, float a4,
                                     float a5, float a6, float a7, float a8) {
    return 0.0625f * (a0 + a8) + 0.25f * (a1 + a7) + 0.25f * (a2 + a6)
         - 0.25f * (a3 + a5) - 0.625f * a4;
}

__global__ void __launch_bounds__(128, 12)
delta_layer_kernel(const float2* __restrict__ x, float2* __restrict__ out) {
    const int d2    = threadIdx.x;       // 0..127
    const int chunk = blockIdx.x;        // 0..127
    const int b     = blockIdx.y;
    const int t0    = chunk * L_N;

    const float2* __restrict__ xb = x   + (size_t)b * T_N * D2_N  + d2;
    float2*       __restrict__ ob = out + (size_t)b * T_N * OD2_N + d2;

    if (chunk != 0 && chunk != CHUNKS - 1) {
        // ---- interior fast path ----
        // ring r0..r8 = x[t0-4 .. t0+4]; all in-bounds (1 <= chunk <= 126)
        float2 r0 = __ldg(xb + (size_t)(t0 - 4) * D2_N);
        float2 r1 = __ldg(xb + (size_t)(t0 - 3) * D2_N);
        float2 r2 = __ldg(xb + (size_t)(t0 - 2) * D2_N);
        float2 r3 = __ldg(xb + (size_t)(t0 - 1) * D2_N);
        float2 r4 = __ldg(xb + (size_t)(t0    ) * D2_N);
        float2 r5 = __ldg(xb + (size_t)(t0 + 1) * D2_N);
        float2 r6 = __ldg(xb + (size_t)(t0 + 2) * D2_N);
        float2 r7 = __ldg(xb + (size_t)(t0 + 3) * D2_N);
        float2 r8 = __ldg(xb + (size_t)(t0 + 4) * D2_N);

#pragma unroll
        for (int g = 0; g < L_N; g += G_N) {
            // batch-prefetch rows t0+g+5 .. t0+g+8 (4 independent LDGs in flight)
            // max index: g=28 -> t0+36 <= 4068 < T for interior chunks
            float2 p0 = __ldg(xb + (size_t)(t0 + g + 5) * D2_N);
            float2 p1 = __ldg(xb + (size_t)(t0 + g + 6) * D2_N);
            float2 p2 = __ldg(xb + (size_t)(t0 + g + 7) * D2_N);
            float2 p3 = __ldg(xb + (size_t)(t0 + g + 8) * D2_N);

#pragma unroll
            for (int k = 0; k < G_N; ++k) {
                const int t = t0 + g + k;
                const size_t orow = (size_t)t * OD2_N;

                __stcs(ob + orow, r4);                               // x
                __stcs(ob + orow + D2_N, f2_delta(r2, r3, r5, r6));  // delta

                float2 dd;
                dd.x = dd9(r0.x, r1.x, r2.x, r3.x, r4.x, r5.x, r6.x, r7.x, r8.x);
                dd.y = dd9(r0.y, r1.y, r2.y, r3.y, r4.y, r5.y, r6.y, r7.y, r8.y);
                __stcs(ob + orow + 2 * D2_N, dd);                    // double delta

                r0 = r1; r1 = r2; r2 = r3; r3 = r4; r4 = r5; r5 = r6; r6 = r7; r7 = r8;
                r8 = (k == 0) ? p0 : (k == 1) ? p1 : (k == 2) ? p2 : p3;
            }
        }
    } else {
        // ---- edge path: generic clamped math (2 of 128 chunks) ----
        auto LD = [&](int t) -> float2 {
            t = t < 0 ? 0 : (t > T_N - 1 ? T_N - 1 : t);
            return __ldg(xb + (size_t)t * D2_N);
        };
        auto DELTA_AT = [&](int s) -> float2 {
            s = s < 0 ? 0 : (s > T_N - 1 ? T_N - 1 : s);
            return f2_delta(LD(s - 2), LD(s - 1), LD(s + 1), LD(s + 2));
        };

        for (int i = 0; i < L_N; ++i) {
            const int t = t0 + i;
            const size_t orow = (size_t)t * OD2_N;
            ob[orow]         = LD(t);
            ob[orow + D2_N]  = DELTA_AT(t);
            ob[orow + 2 * D2_N] =
                f2_delta(DELTA_AT(t - 2), DELTA_AT(t - 1), DELTA_AT(t + 1), DELTA_AT(t + 2));
        }
    }
}

extern "C" void kernel_launch(void* const* d_in, const int* in_sizes, int n_in,
                              void* d_out, int out_size) {
    const float2* x = (const float2*)d_in[0];
    float2* out     = (float2*)d_out;
    // d_in[1] = window (always 2) — baked in.

    dim3 block(D2_N, 1);        // 128 threads = 1 chunk
    dim3 grid(CHUNKS, B_N);     // (128, 32) = 4096 blocks
    delta_layer_kernel<<<grid, block>>>(x, out);
}